// round 15
// baseline (speedup 1.0000x reference)
#include <cuda_runtime.h>
#include <cuda_bf16.h>
#include <math.h>
#include <stdint.h>

// ---------------------------------------------------------------------------
// Problem constants
// ---------------------------------------------------------------------------
#define BATCH   8
#define SEQ     1024
#define EMBED   768
#define HEADS   12
#define HD      64
#define HIDDEN  3072
#define MTOK    (BATCH * SEQ)          // 8192 tokens
#define QKVC    (3 * EMBED)            // 2304

// ---------------------------------------------------------------------------
// Scratch (static __device__: allocation-free per harness rules)
// ---------------------------------------------------------------------------
__device__ __align__(16) float         g_x1  [(size_t)MTOK * EMBED];
__device__ __align__(16) __nv_bfloat16 g_qkvb[(size_t)MTOK * QKVC];    // bf16 qkv (Q pre-scaled)
__device__ __align__(16) __nv_bfloat16 g_as  [(size_t)MTOK * EMBED];
__device__ __align__(16) __nv_bfloat16 g_ctxs[(size_t)MTOK * EMBED];
__device__ __align__(16) __nv_bfloat16 g_f1s [(size_t)MTOK * HIDDEN];
__device__ __align__(16) __nv_bfloat16 g_wq  [(size_t)QKVC  * EMBED];
__device__ __align__(16) __nv_bfloat16 g_wp  [(size_t)EMBED * EMBED];
__device__ __align__(16) __nv_bfloat16 g_w1  [(size_t)HIDDEN* EMBED];
__device__ __align__(16) __nv_bfloat16 g_w2  [(size_t)EMBED * HIDDEN];

// ---------------------------------------------------------------------------
// Shared PTX helpers
// ---------------------------------------------------------------------------
__device__ __forceinline__ void ldm4(uint32_t* r, uint32_t addr) {
    asm volatile("ldmatrix.sync.aligned.m8n8.x4.shared.b16 {%0,%1,%2,%3}, [%4];"
        : "=r"(r[0]), "=r"(r[1]), "=r"(r[2]), "=r"(r[3]) : "r"(addr));
}
__device__ __forceinline__ void ldm4t(uint32_t* r, uint32_t addr) {
    asm volatile("ldmatrix.sync.aligned.m8n8.x4.trans.shared.b16 {%0,%1,%2,%3}, [%4];"
        : "=r"(r[0]), "=r"(r[1]), "=r"(r[2]), "=r"(r[3]) : "r"(addr));
}
__device__ __forceinline__ void mma16816(float* c, const uint32_t* a, uint32_t b0, uint32_t b1) {
    asm volatile("mma.sync.aligned.m16n8k16.row.col.f32.bf16.bf16.f32 "
        "{%0,%1,%2,%3}, {%4,%5,%6,%7}, {%8,%9}, {%0,%1,%2,%3};"
        : "+f"(c[0]), "+f"(c[1]), "+f"(c[2]), "+f"(c[3])
        : "r"(a[0]), "r"(a[1]), "r"(a[2]), "r"(a[3]), "r"(b0), "r"(b1));
}
__device__ __forceinline__ uint32_t packbf(float lo, float hi) {
    __nv_bfloat162 t = __floats2bfloat162_rn(lo, hi);
    return *(uint32_t*)&t;
}
__device__ __forceinline__ void cpasync16(uint32_t dst, const void* src) {
    asm volatile("cp.async.cg.shared.global [%0], [%1], 16;" :: "r"(dst), "l"(src));
}
__device__ __forceinline__ void cp_commit() { asm volatile("cp.async.commit_group;"); }
template<int N> __device__ __forceinline__ void cp_wait() {
    asm volatile("cp.async.wait_group %0;" :: "n"(N));
}

// ---------------------------------------------------------------------------
// Fused weight convert: all four weight tensors fp32 -> bf16 in one launch
// ---------------------------------------------------------------------------
#define WQ_N ((size_t)QKVC  * EMBED)
#define WP_N ((size_t)EMBED * EMBED)
#define W1_N ((size_t)HIDDEN * EMBED)
#define W2_N ((size_t)EMBED * HIDDEN)

__global__ void wconv_all(const float* __restrict__ wq, const float* __restrict__ wp,
                          const float* __restrict__ w1, const float* __restrict__ w2,
                          __nv_bfloat16* __restrict__ oq, __nv_bfloat16* __restrict__ op,
                          __nv_bfloat16* __restrict__ o1, __nv_bfloat16* __restrict__ o2)
{
    const size_t total = WQ_N + WP_N + W1_N + W2_N;
    size_t i = ((size_t)blockIdx.x * blockDim.x + threadIdx.x) * 4;
    size_t stride = (size_t)gridDim.x * blockDim.x * 4;
    for (; i < total; i += stride) {
        const float* src; __nv_bfloat16* dst; size_t off = i;
        if (off < WQ_N)                         { src = wq; dst = oq; }
        else if ((off -= WQ_N) < WP_N)          { src = wp; dst = op; }
        else if ((off -= WP_N) < W1_N)          { src = w1; dst = o1; }
        else { off -= W1_N;                       src = w2; dst = o2; }
        float4 v = *(const float4*)&src[off];
        __nv_bfloat162 p0, p1;
        p0.x = __float2bfloat16(v.x); p0.y = __float2bfloat16(v.y);
        p1.x = __float2bfloat16(v.z); p1.y = __float2bfloat16(v.w);
        *(__nv_bfloat162*)&dst[off]     = p0;
        *(__nv_bfloat162*)&dst[off + 2] = p1;
    }
}

// ---------------------------------------------------------------------------
// LayerNorm -> bf16 row (768)
// ---------------------------------------------------------------------------
__global__ __launch_bounds__(256) void ln_kernel(
    const float* __restrict__ x, const float* __restrict__ g,
    const float* __restrict__ bvec, __nv_bfloat16* __restrict__ out)
{
    int row = blockIdx.x;
    const float* xr = x + (size_t)row * EMBED;
    int t = threadIdx.x;

    float v0 = xr[t], v1 = xr[t + 256], v2 = xr[t + 512];
    float s  = v0 + v1 + v2;
    float ss = v0 * v0 + v1 * v1 + v2 * v2;

    __shared__ float red0[8], red1[8];
    int lane = t & 31, wid = t >> 5;
    #pragma unroll
    for (int o = 16; o; o >>= 1) {
        s  += __shfl_xor_sync(0xffffffffu, s,  o);
        ss += __shfl_xor_sync(0xffffffffu, ss, o);
    }
    if (lane == 0) { red0[wid] = s; red1[wid] = ss; }
    __syncthreads();
    if (t < 32) {
        s  = (t < 8) ? red0[t] : 0.f;
        ss = (t < 8) ? red1[t] : 0.f;
        #pragma unroll
        for (int o = 4; o; o >>= 1) {
            s  += __shfl_xor_sync(0xffffffffu, s,  o);
            ss += __shfl_xor_sync(0xffffffffu, ss, o);
        }
        if (t == 0) { red0[0] = s; red1[0] = ss; }
    }
    __syncthreads();
    float mean = red0[0] * (1.0f / EMBED);
    float var  = red1[0] * (1.0f / EMBED) - mean * mean;
    float rstd = rsqrtf(var + 1e-5f);

    __nv_bfloat16* orow = out + (size_t)row * EMBED;
    orow[t]       = __float2bfloat16((v0 - mean) * rstd * g[t]       + bvec[t]);
    orow[t + 256] = __float2bfloat16((v1 - mean) * rstd * g[t + 256] + bvec[t + 256]);
    orow[t + 512] = __float2bfloat16((v2 - mean) * rstd * g[t + 512] + bvec[t + 512]);
}

// ---------------------------------------------------------------------------
// bf16 GEMM, raw mma.m16n8k16, warp tile 64x64, 4 warps, 128x128 CTA tile.
// 3-stage cp.async pipeline. Direct register epilogue.
// EPI: 0 = bias -> fp32 C; 1 = bias+Res -> fp32 C; 2 = bias+GELU -> bf16 Cs
//      3 = bias -> bf16 Cs, cols < EMBED scaled by 0.125 (Q pre-scale for attn)
// ---------------------------------------------------------------------------
#define LDS 40
#define STAGES 3
#define STAGE_ELEMS (128 * LDS)
#define GEMM_SMEM (STAGES * 2 * STAGE_ELEMS * 2)   // 61440 B

template<int EPI>
__global__ __launch_bounds__(128, 2) void tc_gemm(
    const __nv_bfloat16* __restrict__ A, const __nv_bfloat16* __restrict__ B,
    const float* __restrict__ bias, const float* __restrict__ Res,
    float* __restrict__ C, __nv_bfloat16* __restrict__ Cs,
    int N, int Kp)
{
    extern __shared__ __align__(16) char dynsmem[];
    __nv_bfloat16* Asm = (__nv_bfloat16*)dynsmem;
    __nv_bfloat16* Bsm = Asm + STAGES * STAGE_ELEMS;
    uint32_t sAu = (uint32_t)__cvta_generic_to_shared(Asm);
    uint32_t sBu = (uint32_t)__cvta_generic_to_shared(Bsm);

    int tid  = threadIdx.x;
    int warp = tid >> 5, lane = tid & 31;
    int wm = warp >> 1, wn = warp & 1;
    int bm = blockIdx.y * 128, bn = blockIdx.x * 128;

    const __nv_bfloat16* Agp = A + (size_t)(bm + tid) * Kp;
    const __nv_bfloat16* Bgp = B + (size_t)(bn + tid) * Kp;
    uint32_t dstA = sAu + (uint32_t)(tid * LDS) * 2;
    uint32_t dstB = sBu + (uint32_t)(tid * LDS) * 2;

    auto load_chunk = [&](int chunk, int st) {
        uint32_t so = (uint32_t)st * STAGE_ELEMS * 2;
        const __nv_bfloat16* a = Agp + (chunk << 5);
        const __nv_bfloat16* b = Bgp + (chunk << 5);
        #pragma unroll
        for (int seg = 0; seg < 4; ++seg) {
            cpasync16(dstA + so + seg * 16, a + seg * 8);
            cpasync16(dstB + so + seg * 16, b + seg * 8);
        }
    };

    float acc[4][8][4];
    #pragma unroll
    for (int mi = 0; mi < 4; ++mi)
        #pragma unroll
        for (int nj = 0; nj < 8; ++nj)
            #pragma unroll
            for (int c = 0; c < 4; ++c) acc[mi][nj][c] = 0.f;

    int nk = Kp >> 5;
    int krow = ((lane >> 4) << 3) + (lane & 7);
    int kcb  = (lane & 8);
    int arow = lane & 15;
    int acb  = (lane >> 4) << 3;

    #pragma unroll
    for (int s = 0; s < STAGES - 1; ++s) {
        load_chunk(s, s);
        cp_commit();
    }

    for (int t = 0; t < nk; ++t) {
        cp_wait<STAGES - 2>();
        __syncthreads();

        int nxt = t + STAGES - 1;
        if (nxt < nk) load_chunk(nxt, nxt % STAGES);
        cp_commit();

        int st = t % STAGES;
        uint32_t aBase = sAu + (uint32_t)(st * STAGE_ELEMS) * 2;
        uint32_t bBase = sBu + (uint32_t)(st * STAGE_ELEMS) * 2;
        #pragma unroll
        for (int ks = 0; ks < 2; ++ks) {
            uint32_t af[4][4];
            #pragma unroll
            for (int mi = 0; mi < 4; ++mi)
                ldm4(af[mi], aBase + (uint32_t)((wm * 64 + mi * 16 + arow) * LDS + ks * 16 + acb) * 2);
            #pragma unroll
            for (int nb = 0; nb < 4; ++nb) {
                uint32_t kb[4];
                ldm4(kb, bBase + (uint32_t)((wn * 64 + nb * 16 + krow) * LDS + ks * 16 + kcb) * 2);
                #pragma unroll
                for (int mi = 0; mi < 4; ++mi) {
                    mma16816(acc[mi][2 * nb],     af[mi], kb[0], kb[1]);
                    mma16816(acc[mi][2 * nb + 1], af[mi], kb[2], kb[3]);
                }
            }
        }
    }

    // ---- direct register epilogue ----
    int r  = lane >> 2;
    int cc = (lane & 3) << 1;
    #pragma unroll
    for (int mi = 0; mi < 4; ++mi) {
        int row0 = bm + wm * 64 + mi * 16 + r;
        #pragma unroll
        for (int nj = 0; nj < 8; ++nj) {
            int col = bn + wn * 64 + nj * 8 + cc;
            float2 bb = *(const float2*)&bias[col];
            float v0 = acc[mi][nj][0] + bb.x;
            float v1 = acc[mi][nj][1] + bb.y;
            float v2 = acc[mi][nj][2] + bb.x;
            float v3 = acc[mi][nj][3] + bb.y;
            size_t off0 = (size_t)row0 * N + col;
            size_t off1 = off0 + (size_t)8 * N;
            if (EPI == 2) {
                v0 = 0.5f * v0 * (1.0f + erff(v0 * 0.70710678118654752f));
                v1 = 0.5f * v1 * (1.0f + erff(v1 * 0.70710678118654752f));
                v2 = 0.5f * v2 * (1.0f + erff(v2 * 0.70710678118654752f));
                v3 = 0.5f * v3 * (1.0f + erff(v3 * 0.70710678118654752f));
                *(uint32_t*)&Cs[off0] = packbf(v0, v1);
                *(uint32_t*)&Cs[off1] = packbf(v2, v3);
            } else if (EPI == 3) {
                float sc = (col < EMBED) ? 0.125f : 1.0f;   // exact pow2, Q block only
                *(uint32_t*)&Cs[off0] = packbf(v0 * sc, v1 * sc);
                *(uint32_t*)&Cs[off1] = packbf(v2 * sc, v3 * sc);
            } else {
                if (EPI == 1) {
                    float2 r0 = *(const float2*)&Res[off0];
                    float2 r1 = *(const float2*)&Res[off1];
                    v0 += r0.x; v1 += r0.y; v2 += r1.x; v3 += r1.y;
                }
                *(float2*)&C[off0] = make_float2(v0, v1);
                *(float2*)&C[off1] = make_float2(v2, v3);
            }
        }
    }
}

// ---------------------------------------------------------------------------
// FlashAttention-2 attention, bf16 qkv input (Q pre-scaled in GEMM epilogue).
// K/V tiles streamed with double-buffered cp.async into ldmatrix-ready smem.
// grid = (SEQ/64, BATCH*HEADS), block = 128 (4 warps x 16 queries).
// ---------------------------------------------------------------------------
#define AST 72
#define KVSTAGE (64 * AST)   // bf16 elems per K or V stage

__global__ __launch_bounds__(128) void attn_kernel(
    const __nv_bfloat16* __restrict__ qkv, __nv_bfloat16* __restrict__ ctxs)
{
    __shared__ __align__(16) __nv_bfloat16 Qs[64 * AST];
    __shared__ __align__(16) __nv_bfloat16 Ks[2][KVSTAGE];
    __shared__ __align__(16) __nv_bfloat16 Vs[2][KVSTAGE];

    int bh = blockIdx.y;
    int b  = bh / HEADS;
    int h  = bh % HEADS;
    int q0 = blockIdx.x * 64;
    int tid = threadIdx.x, warp = tid >> 5, lane = tid & 31;
    int hq = h * HD;
    const __nv_bfloat16* base = qkv + (size_t)(b * SEQ) * QKVC;

    uint32_t ksu = (uint32_t)__cvta_generic_to_shared(&Ks[0][0]);
    uint32_t vsu = (uint32_t)__cvta_generic_to_shared(&Vs[0][0]);

    // ---- load Q tile (already bf16, already scaled): 64 rows x 128B ----
    #pragma unroll
    for (int i = 0; i < 4; ++i) {
        int idx = tid + i * 128;
        int r = idx >> 3, seg = idx & 7;
        *(float4*)&Qs[r * AST + seg * 8] =
            *(const float4*)(base + (size_t)(q0 + r) * QKVC + hq + seg * 8);
    }
    __syncthreads();

    // ---- Q A-frags, register-resident ----
    uint32_t qa[4][4];
    {
        int qr = warp * 16 + (lane & 15);
        int cb = (lane >> 4) << 3;
        #pragma unroll
        for (int kk = 0; kk < 4; ++kk)
            ldm4(qa[kk], (uint32_t)__cvta_generic_to_shared(&Qs[qr * AST + kk * 16 + cb]));
    }

    // cp.async K/V tile loader: 512 16B segments per matrix, 4 per thread
    int lr  = tid >> 1;                       // 0..63 (row, 2 threads/row)
    int ls  = (tid & 1) << 2;                 // seg 0 or 4
    auto loadKV = [&](int t, int st) {
        const __nv_bfloat16* trow = base + (size_t)(t * 64 + lr) * QKVC + hq;
        uint32_t kd = ksu + (uint32_t)(st * KVSTAGE + lr * AST + ls * 8) * 2;
        uint32_t vd = vsu + (uint32_t)(st * KVSTAGE + lr * AST + ls * 8) * 2;
        #pragma unroll
        for (int sgi = 0; sgi < 4; ++sgi) {
            cpasync16(kd + sgi * 16, trow + EMBED     + (ls + sgi) * 8);
            cpasync16(vd + sgi * 16, trow + 2 * EMBED + (ls + sgi) * 8);
        }
    };

    float o[8][4];
    #pragma unroll
    for (int j = 0; j < 8; ++j)
        #pragma unroll
        for (int c = 0; c < 4; ++c) o[j][c] = 0.f;
    float mA = -1e30f, mB = -1e30f, lA = 0.f, lB = 0.f;

    int krow = ((lane >> 4) << 3) + (lane & 7);
    int kcb  = (lane & 8);
    int vrow = (lane & 15);
    int vcb  = (lane >> 4) << 3;

    loadKV(0, 0);
    cp_commit();

    for (int t = 0; t < 16; ++t) {
        __syncthreads();              // prev compute done before overwriting stage (t+1)&1
        if (t + 1 < 16) loadKV(t + 1, (t + 1) & 1);
        cp_commit();
        cp_wait<1>();                 // tile t resident
        __syncthreads();

        int st = t & 1;
        // ---- S = Q K^T ----
        float s[8][4];
        #pragma unroll
        for (int j = 0; j < 8; ++j)
            #pragma unroll
            for (int c = 0; c < 4; ++c) s[j][c] = 0.f;
        #pragma unroll
        for (int kk = 0; kk < 4; ++kk) {
            #pragma unroll
            for (int j = 0; j < 8; j += 2) {
                uint32_t kb[4];
                ldm4(kb, (uint32_t)__cvta_generic_to_shared(
                    &Ks[st][(j * 8 + krow) * AST + kk * 16 + kcb]));
                mma16816(s[j],     qa[kk], kb[0], kb[1]);
                mma16816(s[j + 1], qa[kk], kb[2], kb[3]);
            }
        }

        // ---- online softmax ----
        float rmA = -1e30f, rmB = -1e30f;
        #pragma unroll
        for (int j = 0; j < 8; ++j) {
            rmA = fmaxf(rmA, fmaxf(s[j][0], s[j][1]));
            rmB = fmaxf(rmB, fmaxf(s[j][2], s[j][3]));
        }
        rmA = fmaxf(rmA, __shfl_xor_sync(0xffffffffu, rmA, 1));
        rmA = fmaxf(rmA, __shfl_xor_sync(0xffffffffu, rmA, 2));
        rmB = fmaxf(rmB, __shfl_xor_sync(0xffffffffu, rmB, 1));
        rmB = fmaxf(rmB, __shfl_xor_sync(0xffffffffu, rmB, 2));
        float mnA = fmaxf(mA, rmA), mnB = fmaxf(mB, rmB);
        float corrA = __expf(mA - mnA), corrB = __expf(mB - mnB);
        mA = mnA; mB = mnB;

        float rsA = 0.f, rsB = 0.f;
        #pragma unroll
        for (int j = 0; j < 8; ++j) {
            s[j][0] = __expf(s[j][0] - mA);
            s[j][1] = __expf(s[j][1] - mA);
            s[j][2] = __expf(s[j][2] - mB);
            s[j][3] = __expf(s[j][3] - mB);
            rsA += s[j][0] + s[j][1];
            rsB += s[j][2] + s[j][3];
        }
        rsA += __shfl_xor_sync(0xffffffffu, rsA, 1);
        rsA += __shfl_xor_sync(0xffffffffu, rsA, 2);
        rsB += __shfl_xor_sync(0xffffffffu, rsB, 1);
        rsB += __shfl_xor_sync(0xffffffffu, rsB, 2);
        lA = lA * corrA + rsA;
        lB = lB * corrB + rsB;
        #pragma unroll
        for (int j = 0; j < 8; ++j) {
            o[j][0] *= corrA; o[j][1] *= corrA;
            o[j][2] *= corrB; o[j][3] *= corrB;
        }

        // ---- P frags + PV ----
        uint32_t pa[4][4];
        #pragma unroll
        for (int kk = 0; kk < 4; ++kk) {
            pa[kk][0] = packbf(s[2 * kk][0],     s[2 * kk][1]);
            pa[kk][1] = packbf(s[2 * kk][2],     s[2 * kk][3]);
            pa[kk][2] = packbf(s[2 * kk + 1][0], s[2 * kk + 1][1]);
            pa[kk][3] = packbf(s[2 * kk + 1][2], s[2 * kk + 1][3]);
        }
        #pragma unroll
        for (int kk = 0; kk < 4; ++kk) {
            #pragma unroll
            for (int d8 = 0; d8 < 8; d8 += 2) {
                uint32_t vb[4];
                ldm4t(vb, (uint32_t)__cvta_generic_to_shared(
                    &Vs[st][(16 * kk + vrow) * AST + d8 * 8 + vcb]));
                mma16816(o[d8],     pa[kk], vb[0], vb[1]);
                mma16816(o[d8 + 1], pa[kk], vb[2], vb[3]);
            }
        }
    }

    float iA = 1.0f / lA, iB = 1.0f / lB;
    int rowA = lane >> 2;
    int qA = q0 + warp * 16 + rowA;
    int cA = hq + (lane & 3) * 2;
    __nv_bfloat16* outA = ctxs + ((size_t)(b * SEQ) + qA) * EMBED;
    __nv_bfloat16* outB = outA + (size_t)8 * EMBED;
    #pragma unroll
    for (int j = 0; j < 8; ++j) {
        *(uint32_t*)&outA[cA + j * 8] = packbf(o[j][0] * iA, o[j][1] * iA);
        *(uint32_t*)&outB[cA + j * 8] = packbf(o[j][2] * iB, o[j][3] * iB);
    }
}

// ---------------------------------------------------------------------------
// Launch
// ---------------------------------------------------------------------------
extern "C" void kernel_launch(void* const* d_in, const int* in_sizes, int n_in,
                              void* d_out, int out_size)
{
    const float* x      = (const float*)d_in[0];
    const float* ln1_g  = (const float*)d_in[1];
    const float* ln1_b  = (const float*)d_in[2];
    const float* qkv_w  = (const float*)d_in[3];
    const float* qkv_b  = (const float*)d_in[4];
    const float* proj_w = (const float*)d_in[5];
    const float* proj_b = (const float*)d_in[6];
    const float* ln2_g  = (const float*)d_in[7];
    const float* ln2_b  = (const float*)d_in[8];
    const float* fc1_w  = (const float*)d_in[9];
    const float* fc1_b  = (const float*)d_in[10];
    const float* fc2_w  = (const float*)d_in[11];
    const float* fc2_b  = (const float*)d_in[12];
    float* out = (float*)d_out;

    float *p_x1;
    __nv_bfloat16 *p_qkvb, *p_as, *p_ctxs, *p_f1s, *p_wq, *p_wp, *p_w1, *p_w2;
    cudaGetSymbolAddress((void**)&p_x1,   g_x1);
    cudaGetSymbolAddress((void**)&p_qkvb, g_qkvb);
    cudaGetSymbolAddress((void**)&p_as,   g_as);
    cudaGetSymbolAddress((void**)&p_ctxs, g_ctxs);
    cudaGetSymbolAddress((void**)&p_f1s,  g_f1s);
    cudaGetSymbolAddress((void**)&p_wq,   g_wq);
    cudaGetSymbolAddress((void**)&p_wp,   g_wp);
    cudaGetSymbolAddress((void**)&p_w1,   g_w1);
    cudaGetSymbolAddress((void**)&p_w2,   g_w2);

    cudaFuncSetAttribute(tc_gemm<1>, cudaFuncAttributeMaxDynamicSharedMemorySize, GEMM_SMEM);
    cudaFuncSetAttribute(tc_gemm<2>, cudaFuncAttributeMaxDynamicSharedMemorySize, GEMM_SMEM);
    cudaFuncSetAttribute(tc_gemm<3>, cudaFuncAttributeMaxDynamicSharedMemorySize, GEMM_SMEM);

    wconv_all<<<1024, 256>>>(qkv_w, proj_w, fc1_w, fc2_w, p_wq, p_wp, p_w1, p_w2);

    // 1) LN1 -> bf16
    ln_kernel<<<MTOK, 256>>>(x, ln1_g, ln1_b, p_as);
    // 2) QKV GEMM -> bf16 (Q cols pre-scaled by 1/8)
    tc_gemm<3><<<dim3(QKVC / 128, MTOK / 128), 128, GEMM_SMEM>>>(
        p_as, p_wq, qkv_b, nullptr, nullptr, p_qkvb, QKVC, EMBED);
    // 3) flash attention (bf16 in/out, cp.async K/V pipeline)
    attn_kernel<<<dim3(SEQ / 64, BATCH * HEADS), 128>>>(p_qkvb, p_ctxs);
    // 4) proj GEMM + residual -> fp32 x1
    tc_gemm<1><<<dim3(EMBED / 128, MTOK / 128), 128, GEMM_SMEM>>>(
        p_ctxs, p_wp, proj_b, x, p_x1, nullptr, EMBED, EMBED);
    // 5) LN2 -> bf16
    ln_kernel<<<MTOK, 256>>>(p_x1, ln2_g, ln2_b, p_as);
    // 6) FC1 GEMM + GELU -> bf16
    tc_gemm<2><<<dim3(HIDDEN / 128, MTOK / 128), 128, GEMM_SMEM>>>(
        p_as, p_w1, fc1_b, nullptr, nullptr, p_f1s, HIDDEN, EMBED);
    // 7) FC2 GEMM + residual -> final fp32 output
    tc_gemm<1><<<dim3(EMBED / 128, MTOK / 128), 128, GEMM_SMEM>>>(
        p_f1s, p_w2, fc2_b, p_x1, out, nullptr, EMBED, HIDDEN);
}